// round 8
// baseline (speedup 1.0000x reference)
#include <cuda_runtime.h>

// Problem constants
#define NB 16
#define NT 256
#define NK 128
#define ND 256   // D_E == D_K == 256
#define NU 128
#define TPT 16   // t-rows per fused block

// Scratch (allocation-free rule: __device__ global)
__device__ float g_kpT[NB * NU * NK];   // [b][u][k]  (k-proj + b2, transposed)

__device__ __forceinline__ float tanh_fast(float x) {
    float y;
    asm("tanh.approx.f32 %0, %1;" : "=f"(y) : "f"(x));
    return y;
}
// Packed f32x2 FMA (sm_100+): one FFMA2 = 2 fp32 FMAs on the fma pipe.
__device__ __forceinline__ unsigned long long fma2(unsigned long long a,
                                                   unsigned long long b,
                                                   unsigned long long c) {
    unsigned long long d;
    asm("fma.rn.f32x2 %0, %1, %2, %3;" : "=l"(d) : "l"(a), "l"(b), "l"(c));
    return d;
}
__device__ __forceinline__ float2 u2f(unsigned long long v) {
    float2 r;
    asm("mov.b64 {%0, %1}, %2;" : "=f"(r.x), "=f"(r.y) : "l"(v));
    return r;
}

// ---------------------------------------------------------------------------
// kp-projection: kp = knw @ W2 + b2, stored transposed g_kpT[b][u][k].
// 128 blocks x 256 threads, 16 k-rows x 128 u-cols per block.
// ---------------------------------------------------------------------------
__global__ __launch_bounds__(256) void kproj_kernel(
    const float* __restrict__ knw, const float* __restrict__ W2,
    const float* __restrict__ b2)
{
    const int row0 = blockIdx.x * 16;   // row in [0, 2048)

    __shared__ float2 As2[16][32];      // duplicated (a,a)
    __shared__ float  Bs[32][128];

    const int tid = threadIdx.x;
    const int tx  = tid & 31;
    const int ty  = tid >> 5;

    unsigned long long a00 = 0ull, a01 = 0ull;
    unsigned long long a10 = 0ull, a11 = 0ull;

    for (int kc = 0; kc < ND; kc += 32) {
        if (tid < 128) {
            int r  = tid >> 3;
            int c4 = tid & 7;
            float4 a = *(const float4*)&knw[(row0 + r) * ND + kc + c4 * 4];
            As2[r][c4 * 4 + 0] = make_float2(a.x, a.x);
            As2[r][c4 * 4 + 1] = make_float2(a.y, a.y);
            As2[r][c4 * 4 + 2] = make_float2(a.z, a.z);
            As2[r][c4 * 4 + 3] = make_float2(a.w, a.w);
        }
        #pragma unroll
        for (int i = 0; i < 4; i++) {
            int lin = tid + i * 256;
            int r   = lin >> 5;
            int c4  = lin & 31;
            *(float4*)&Bs[r][c4 * 4] = *(const float4*)&W2[(kc + r) * NU + c4 * 4];
        }
        __syncthreads();

        #pragma unroll
        for (int kk = 0; kk < 32; kk++) {
            ulonglong2 bv = *(const ulonglong2*)&Bs[kk][tx * 4];
            unsigned long long av0 = *(const unsigned long long*)&As2[ty * 2 + 0][kk];
            unsigned long long av1 = *(const unsigned long long*)&As2[ty * 2 + 1][kk];
            a00 = fma2(av0, bv.x, a00);
            a01 = fma2(av0, bv.y, a01);
            a10 = fma2(av1, bv.x, a10);
            a11 = fma2(av1, bv.y, a11);
        }
        __syncthreads();
    }

    float2 r00 = u2f(a00), r01 = u2f(a01), r10 = u2f(a10), r11 = u2f(a11);
    float4 bb = *(const float4*)&b2[tx * 4];
    float4 acc0 = make_float4(r00.x + bb.x, r00.y + bb.y, r01.x + bb.z, r01.y + bb.w);
    float4 acc1 = make_float4(r10.x + bb.x, r10.y + bb.y, r11.x + bb.z, r11.y + bb.w);

    const int r0 = row0 + ty * 2;
    const int b0 = r0 >> 7;
    const int k0 = r0 & 127;
    float* dst = &g_kpT[b0 * NU * NK];
    dst[(4 * tx + 0) * NK + k0] = acc0.x;
    dst[(4 * tx + 1) * NK + k0] = acc0.y;
    dst[(4 * tx + 2) * NK + k0] = acc0.z;
    dst[(4 * tx + 3) * NK + k0] = acc0.w;
    dst[(4 * tx + 0) * NK + k0 + 1] = acc1.x;
    dst[(4 * tx + 1) * NK + k0 + 1] = acc1.y;
    dst[(4 * tx + 2) * NK + k0 + 1] = acc1.z;
    dst[(4 * tx + 3) * NK + k0 + 1] = acc1.w;
}

// ---------------------------------------------------------------------------
// Fused e-proj + score + softmax + context.
// Grid (NT/TPT, NB) = 256 blocks, 256 threads (8 warps). smem 90.6 KB
// -> 2 CTAs/SM so one CTA's FMA phases overlap the other's MUFU phase.
// Warp w owns t = {2w, 2w+1} for EVERY phase -> exactly one __syncthreads.
// knowledge is read from L2 in the context phase (no smem copy).
// smem: kpT_s[128u][128k] 64KB | enc_s[16t][256d] 16KB (reused as attn2) |
//       e_s[16t][128u] 8KB | v_s 512B  = 90624 B
// ---------------------------------------------------------------------------
__global__ __launch_bounds__(256) void fused_kernel(
    const float* __restrict__ knw, const float* __restrict__ enc,
    const float* __restrict__ W1, const float* __restrict__ b1,
    const float* __restrict__ V, float* __restrict__ out)
{
    extern __shared__ float smem[];
    float*  kpT_s = smem;                 // 16384 floats
    float*  enc_s = smem + NU * NK;       // 4096 floats (later attn2)
    float*  e_s   = enc_s + TPT * ND;     // 2048 floats
    float*  v_s   = e_s + TPT * NU;       // 128 floats
    float2* attn2 = (float2*)enc_s;       // [16t][128k] duplicated (p,p)

    const int b    = blockIdx.y;
    const int t0   = blockIdx.x * TPT;
    const int tid  = threadIdx.x;
    const int lane = tid & 31;
    const int w    = tid >> 5;

    // ---- stage kpT, enc rows, V (float4 coalesced) ----
    {
        const float4* s = (const float4*)(g_kpT + b * NU * NK);
        float4* d = (float4*)kpT_s;
        #pragma unroll
        for (int i = 0; i < 16; i++) d[tid + i * 256] = s[tid + i * 256];
    }
    {
        const float4* s = (const float4*)(enc + (b * NT + t0) * ND);
        float4* d = (float4*)enc_s;
        #pragma unroll
        for (int i = 0; i < 4; i++) d[tid + i * 256] = s[tid + i * 256];
    }
    if (tid < NU) v_s[tid] = V[tid];
    __syncthreads();   // the ONLY block-wide sync

    const int lt0 = 2 * w;

    // ---- e-proj (FMA pipe, own rows): e[t][u] = b1[u] + enc[t,:] @ W1[:,u] ----
    {
        float4 bb = *(const float4*)&b1[4 * lane];
        float4 acc0 = bb, acc1 = bb;
        const float* er0 = enc_s + (lt0 + 0) * ND;
        const float* er1 = enc_s + (lt0 + 1) * ND;
        #pragma unroll 8
        for (int d = 0; d < ND; d++) {
            float4 wv = *(const float4*)&W1[d * NU + 4 * lane];
            float x0 = er0[d];
            float x1 = er1[d];
            acc0.x += x0 * wv.x; acc0.y += x0 * wv.y;
            acc0.z += x0 * wv.z; acc0.w += x0 * wv.w;
            acc1.x += x1 * wv.x; acc1.y += x1 * wv.y;
            acc1.z += x1 * wv.z; acc1.w += x1 * wv.w;
        }
        ((float4*)&e_s[(lt0 + 0) * NU])[lane] = acc0;
        ((float4*)&e_s[(lt0 + 1) * NU])[lane] = acc1;
    }

    // ---- score (MUFU pipe): lane owns k = 4*lane..+3 ----
    float4 s0 = make_float4(0.f, 0.f, 0.f, 0.f);
    float4 s1 = make_float4(0.f, 0.f, 0.f, 0.f);
    {
        const float* e0 = &e_s[(lt0 + 0) * NU];
        const float* e1 = &e_s[(lt0 + 1) * NU];
        #pragma unroll 4
        for (int u = 0; u < NU; u++) {
            float4 kp = ((const float4*)&kpT_s[u * NK])[lane];
            float vu  = v_s[u];
            float ev0 = e0[u];
            float ev1 = e1[u];
            s0.x += vu * tanh_fast(ev0 + kp.x);
            s0.y += vu * tanh_fast(ev0 + kp.y);
            s0.z += vu * tanh_fast(ev0 + kp.z);
            s0.w += vu * tanh_fast(ev0 + kp.w);
            s1.x += vu * tanh_fast(ev1 + kp.x);
            s1.y += vu * tanh_fast(ev1 + kp.y);
            s1.z += vu * tanh_fast(ev1 + kp.z);
            s1.w += vu * tanh_fast(ev1 + kp.w);
        }
    }

    // ---- softmax over K (in-warp); bV cancels. Write attn2 over OWN enc rows.
    #pragma unroll
    for (int tt = 0; tt < 2; tt++) {
        float4 sv = tt ? s1 : s0;
        float m = fmaxf(fmaxf(sv.x, sv.y), fmaxf(sv.z, sv.w));
        #pragma unroll
        for (int o = 16; o > 0; o >>= 1)
            m = fmaxf(m, __shfl_xor_sync(0xffffffffu, m, o));
        float4 p;
        p.x = __expf(sv.x - m);
        p.y = __expf(sv.y - m);
        p.z = __expf(sv.z - m);
        p.w = __expf(sv.w - m);
        float sum = (p.x + p.y) + (p.z + p.w);
        #pragma unroll
        for (int o = 16; o > 0; o >>= 1)
            sum += __shfl_xor_sync(0xffffffffu, sum, o);
        float inv = __fdividef(1.0f, sum);
        p.x *= inv; p.y *= inv; p.z *= inv; p.w *= inv;
        float2* a = &attn2[(lt0 + tt) * NK + 4 * lane];
        a[0] = make_float2(p.x, p.x);
        a[1] = make_float2(p.y, p.y);
        a[2] = make_float2(p.z, p.z);
        a[3] = make_float2(p.w, p.w);
    }
    __syncwarp();

    // ---- context from L2: out[t][d] = sum_k attn[t][k] * know[k][d] ----
    {
        const float* kb = knw + b * NK * ND;
        unsigned long long c[2][4];
        #pragma unroll
        for (int i = 0; i < 2; i++)
            #pragma unroll
            for (int j = 0; j < 4; j++) c[i][j] = 0ull;

        #pragma unroll 4
        for (int k = 0; k < NK; k++) {
            const float* row = kb + k * ND;
            ulonglong2 lo = ((const ulonglong2*)row)[lane];        // d=4*lane..+3
            ulonglong2 hi = ((const ulonglong2*)row)[lane + 32];   // d=128+4*lane..+3
            #pragma unroll
            for (int tt = 0; tt < 2; tt++) {
                unsigned long long a =
                    *(const unsigned long long*)&attn2[(lt0 + tt) * NK + k];
                c[tt][0] = fma2(a, lo.x, c[tt][0]);
                c[tt][1] = fma2(a, lo.y, c[tt][1]);
                c[tt][2] = fma2(a, hi.x, c[tt][2]);
                c[tt][3] = fma2(a, hi.y, c[tt][3]);
            }
        }

        #pragma unroll
        for (int tt = 0; tt < 2; tt++) {
            float* o = out + (size_t)(b * NT + t0 + lt0 + tt) * ND;
            ((ulonglong2*)o)[lane]      = make_ulonglong2(c[tt][0], c[tt][1]);
            ((ulonglong2*)o)[lane + 32] = make_ulonglong2(c[tt][2], c[tt][3]);
        }
    }
}

// ---------------------------------------------------------------------------
// Launch
// ---------------------------------------------------------------------------
extern "C" void kernel_launch(void* const* d_in, const int* in_sizes, int n_in,
                              void* d_out, int out_size)
{
    const float* knw = (const float*)d_in[0];   // knowledge_onehot [16,128,256]
    const float* enc = (const float*)d_in[1];   // encoder_outputs  [16,256,256]
    const float* W1  = (const float*)d_in[2];
    const float* b1  = (const float*)d_in[3];
    const float* W2  = (const float*)d_in[4];
    const float* b2  = (const float*)d_in[5];
    const float* V   = (const float*)d_in[6];
    // d_in[7] = bV: cancels in softmax. Unused.

    if (n_in >= 2 && in_sizes[0] == NB * NT * ND && in_sizes[1] == NB * NK * ND) {
        const float* tmp = knw; knw = enc; enc = tmp;
    }

    const int smem_bytes = (NU * NK + TPT * ND + TPT * NU + NU) * (int)sizeof(float); // 90624
    cudaFuncSetAttribute(fused_kernel, cudaFuncAttributeMaxDynamicSharedMemorySize,
                         smem_bytes);

    kproj_kernel<<<128, 256>>>(knw, W2, b2);

    dim3 grid(NT / TPT, NB);
    fused_kernel<<<grid, 256, smem_bytes>>>(knw, enc, W1, b1, V, (float*)d_out);

    (void)n_in; (void)out_size;
}

// round 9
// speedup vs baseline: 1.3935x; 1.3935x over previous
#include <cuda_runtime.h>

// Problem constants
#define NB 16
#define NT 256
#define NK 128
#define ND 256   // D_E == D_K == 256
#define NU 128

// Scratch (allocation-free rule: __device__ globals)
// Et duplicated (v,v) so score-phase FFMA2 needs no packing movs.
__device__ float2 g_Et2[NB * NT * NU];   // [b*NT+t][u] : (exp(2e), exp(2e))
__device__ float  g_EkT[NB * NU * NK];   // [b][u][k]   : exp(2kp), transposed

// exp(clamp(2x)) — tanh(a+b) factorization: tanh = 1 - 2/(1 + e^{2a}e^{2b})
__device__ __forceinline__ float eclamp(float x) {
    return __expf(fminf(fmaxf(2.0f * x, -16.0f), 16.0f));
}

// Packed f32x2 ops (sm_100+)
__device__ __forceinline__ unsigned long long fma2(unsigned long long a,
                                                   unsigned long long b,
                                                   unsigned long long c) {
    unsigned long long d;
    asm("fma.rn.f32x2 %0, %1, %2, %3;" : "=l"(d) : "l"(a), "l"(b), "l"(c));
    return d;
}
__device__ __forceinline__ unsigned long long mul2(unsigned long long a,
                                                   unsigned long long b) {
    unsigned long long d;
    asm("mul.rn.f32x2 %0, %1, %2;" : "=l"(d) : "l"(a), "l"(b));
    return d;
}
// packed reciprocal: 2x rcp.approx
__device__ __forceinline__ unsigned long long rcp2(unsigned long long v) {
    unsigned long long r;
    asm("{\n\t"
        ".reg .f32 lo, hi, rl, rh;\n\t"
        "mov.b64 {lo, hi}, %1;\n\t"
        "rcp.approx.f32 rl, lo;\n\t"
        "rcp.approx.f32 rh, hi;\n\t"
        "mov.b64 %0, {rl, rh};\n\t"
        "}" : "=l"(r) : "l"(v));
    return r;
}
__device__ __forceinline__ float2 u2f(unsigned long long v) {
    float2 r;
    asm("mov.b64 {%0, %1}, %2;" : "=f"(r.x), "=f"(r.y) : "l"(v));
    return r;
}

#define ONE2 0x3F8000003F800000ull   // packed (1.0f, 1.0f)

// ---------------------------------------------------------------------------
// Projection kernel (R5-proven scalar tiling + exp epilogue):
//   blocks [0,256):   Et = exp(2*(enc@W1+b1))  -> g_Et2 duplicated
//   blocks [256,384): Ek = exp(2*(knw@W2+b2))  -> g_EkT transposed
// ---------------------------------------------------------------------------
__global__ __launch_bounds__(256) void proj_kernel(
    const float* __restrict__ enc, const float* __restrict__ knw,
    const float* __restrict__ W1, const float* __restrict__ b1,
    const float* __restrict__ W2, const float* __restrict__ b2)
{
    const int blk = blockIdx.x;
    const bool isE = (blk < 256);
    const float* __restrict__ A    = isE ? enc : knw;
    const float* __restrict__ W    = isE ? W1  : W2;
    const float* __restrict__ bias = isE ? b1  : b2;
    const int row0 = (isE ? blk : (blk - 256)) * 16;

    __shared__ float As[16][32];
    __shared__ float Bs[32][128];

    const int tid = threadIdx.x;
    const int tx  = tid & 31;
    const int ty  = tid >> 5;

    float4 acc0 = make_float4(0.f, 0.f, 0.f, 0.f);
    float4 acc1 = make_float4(0.f, 0.f, 0.f, 0.f);

    for (int kc = 0; kc < ND; kc += 32) {
        if (tid < 128) {
            int r  = tid >> 3;
            int c4 = tid & 7;
            float4 a = *(const float4*)&A[(row0 + r) * ND + kc + c4 * 4];
            *(float4*)&As[r][c4 * 4] = a;
        }
        #pragma unroll
        for (int i = 0; i < 4; i++) {
            int lin = tid + i * 256;
            int r   = lin >> 5;
            int c4  = lin & 31;
            *(float4*)&Bs[r][c4 * 4] = *(const float4*)&W[(kc + r) * NU + c4 * 4];
        }
        __syncthreads();

        #pragma unroll
        for (int kk = 0; kk < 32; kk++) {
            float4 bv = *(float4*)&Bs[kk][tx * 4];
            float a0 = As[ty * 2 + 0][kk];
            float a1 = As[ty * 2 + 1][kk];
            acc0.x += a0 * bv.x; acc0.y += a0 * bv.y;
            acc0.z += a0 * bv.z; acc0.w += a0 * bv.w;
            acc1.x += a1 * bv.x; acc1.y += a1 * bv.y;
            acc1.z += a1 * bv.z; acc1.w += a1 * bv.w;
        }
        __syncthreads();
    }

    float4 bb = *(const float4*)&bias[tx * 4];
    // exp(clamp(2*(acc+bias)))
    float e00 = eclamp(acc0.x + bb.x), e01 = eclamp(acc0.y + bb.y);
    float e02 = eclamp(acc0.z + bb.z), e03 = eclamp(acc0.w + bb.w);
    float e10 = eclamp(acc1.x + bb.x), e11 = eclamp(acc1.y + bb.y);
    float e12 = eclamp(acc1.z + bb.z), e13 = eclamp(acc1.w + bb.w);

    const int r0 = row0 + ty * 2;
    if (isE) {
        float4* d0 = (float4*)(g_Et2 + (size_t)(r0 + 0) * NU + 4 * tx);
        d0[0] = make_float4(e00, e00, e01, e01);
        d0[1] = make_float4(e02, e02, e03, e03);
        float4* d1 = (float4*)(g_Et2 + (size_t)(r0 + 1) * NU + 4 * tx);
        d1[0] = make_float4(e10, e10, e11, e11);
        d1[1] = make_float4(e12, e12, e13, e13);
    } else {
        int b0 = r0 >> 7;
        int k0 = r0 & 127;
        float* dst = &g_EkT[b0 * NU * NK];
        dst[(4 * tx + 0) * NK + k0] = e00;
        dst[(4 * tx + 1) * NK + k0] = e01;
        dst[(4 * tx + 2) * NK + k0] = e02;
        dst[(4 * tx + 3) * NK + k0] = e03;
        dst[(4 * tx + 0) * NK + k0 + 1] = e10;
        dst[(4 * tx + 1) * NK + k0 + 1] = e11;
        dst[(4 * tx + 2) * NK + k0 + 1] = e12;
        dst[(4 * tx + 3) * NK + k0 + 1] = e13;
    }
}

// ---------------------------------------------------------------------------
// Fused score + softmax + context (R5-proven structure).
// Grid (NT/32, NB) = 128 blocks, 256 threads (8 warps); warp owns 4 t's,
// lane owns k = 4*lane..+3.
// score[t,k] (up to softmax-invariant const) = sum_u -2*V_u / (1 + Et*Ek),
// two u-terms share one rcp:  V0/q0 + V1/q1 = (V0*q1 + V1*q0) / (q0*q1).
// smem: know[128][256] 128KB | EkT[128][128] 64KB |
//       Et2[32][128] float2 32KB (reused as duplicated attn) | v2 1KB
//       = 230400 B (1 CTA/SM)
// ---------------------------------------------------------------------------
__global__ __launch_bounds__(256) void fused_kernel(
    const float* __restrict__ knw, const float* __restrict__ V,
    float* __restrict__ out)
{
    extern __shared__ float smem[];
    float*  know_s = smem;                          // 32768 floats
    float*  EkT_s  = smem + NK * ND;                // 16384 floats
    float2* Et2_s  = (float2*)(EkT_s + NU * NK);    // 4096 float2
    float2* v2_s   = Et2_s + 32 * NU;               // 128 float2

    const int b    = blockIdx.y;
    const int t0   = blockIdx.x * 32;
    const int tid  = threadIdx.x;
    const int lane = tid & 31;
    const int w    = tid >> 5;

    // ---- stage (float4, coalesced) ----
    {
        const float4* s = (const float4*)(knw + b * NK * ND);
        float4* d = (float4*)know_s;
        #pragma unroll
        for (int i = 0; i < 32; i++) d[tid + i * 256] = s[tid + i * 256];
    }
    {
        const float4* s = (const float4*)(g_EkT + b * NU * NK);
        float4* d = (float4*)EkT_s;
        #pragma unroll
        for (int i = 0; i < 16; i++) d[tid + i * 256] = s[tid + i * 256];
    }
    {
        const float4* s = (const float4*)(g_Et2 + (size_t)(b * NT + t0) * NU);
        float4* d = (float4*)Et2_s;
        #pragma unroll
        for (int i = 0; i < 8; i++) d[tid + i * 256] = s[tid + i * 256];
    }
    if (tid < NU) {
        float vv = -2.0f * V[tid];
        v2_s[tid] = make_float2(vv, vv);
    }
    __syncthreads();

    const int tl = 4 * w;   // first local t this warp owns

    // ---- score: acc[tt][0]=(k0,k1) packed, acc[tt][1]=(k2,k3) packed ----
    unsigned long long acc[4][2];
    #pragma unroll
    for (int tt = 0; tt < 4; tt++) { acc[tt][0] = 0ull; acc[tt][1] = 0ull; }

    #pragma unroll 2
    for (int u = 0; u < NU; u += 2) {
        ulonglong2 ek0 = ((const ulonglong2*)&EkT_s[(u + 0) * NK])[lane];
        ulonglong2 ek1 = ((const ulonglong2*)&EkT_s[(u + 1) * NK])[lane];
        unsigned long long v0 = *(const unsigned long long*)&v2_s[u + 0];
        unsigned long long v1 = *(const unsigned long long*)&v2_s[u + 1];
        #pragma unroll
        for (int tt = 0; tt < 4; tt++) {
            unsigned long long et0 =
                *(const unsigned long long*)&Et2_s[(tl + tt) * NU + u + 0];
            unsigned long long et1 =
                *(const unsigned long long*)&Et2_s[(tl + tt) * NU + u + 1];
            // k-slots (0,1)
            unsigned long long q0 = fma2(et0, ek0.x, ONE2);
            unsigned long long q1 = fma2(et1, ek1.x, ONE2);
            unsigned long long num = fma2(v0, q1, mul2(v1, q0));
            acc[tt][0] = fma2(num, rcp2(mul2(q0, q1)), acc[tt][0]);
            // k-slots (2,3)
            q0 = fma2(et0, ek0.y, ONE2);
            q1 = fma2(et1, ek1.y, ONE2);
            num = fma2(v0, q1, mul2(v1, q0));
            acc[tt][1] = fma2(num, rcp2(mul2(q0, q1)), acc[tt][1]);
        }
    }

    // ---- softmax over K (in-warp); constants cancel ----
    #pragma unroll
    for (int tt = 0; tt < 4; tt++) {
        float2 axy = u2f(acc[tt][0]);
        float2 azw = u2f(acc[tt][1]);
        float4 sv = make_float4(axy.x, axy.y, azw.x, azw.y);
        float m = fmaxf(fmaxf(sv.x, sv.y), fmaxf(sv.z, sv.w));
        #pragma unroll
        for (int o = 16; o > 0; o >>= 1)
            m = fmaxf(m, __shfl_xor_sync(0xffffffffu, m, o));
        float4 p;
        p.x = __expf(sv.x - m);
        p.y = __expf(sv.y - m);
        p.z = __expf(sv.z - m);
        p.w = __expf(sv.w - m);
        float sum = (p.x + p.y) + (p.z + p.w);
        #pragma unroll
        for (int o = 16; o > 0; o >>= 1)
            sum += __shfl_xor_sync(0xffffffffu, sum, o);
        float inv = __fdividef(1.0f, sum);
        p.x *= inv; p.y *= inv; p.z *= inv; p.w *= inv;
        // overwrite OWN Et2 row with duplicated attn (p,p); row = 128 float2
        float2* arow = Et2_s + (tl + tt) * NU;
        arow[4 * lane + 0] = make_float2(p.x, p.x);
        arow[4 * lane + 1] = make_float2(p.y, p.y);
        arow[4 * lane + 2] = make_float2(p.z, p.z);
        arow[4 * lane + 3] = make_float2(p.w, p.w);
    }
    __syncwarp();

    // ---- context (FFMA2): out[t][d] = sum_k attn[t][k] * know[k][d] ----
    unsigned long long c[4][4];
    #pragma unroll
    for (int i = 0; i < 4; i++)
        #pragma unroll
        for (int j = 0; j < 4; j++) c[i][j] = 0ull;

    #pragma unroll 4
    for (int k = 0; k < NK; k++) {
        const float* row = &know_s[k * ND];
        ulonglong2 lo = ((const ulonglong2*)row)[lane];        // d=4*lane..+3
        ulonglong2 hi = ((const ulonglong2*)row)[lane + 32];   // d=128+4*lane..+3
        #pragma unroll
        for (int tt = 0; tt < 4; tt++) {
            unsigned long long a =
                *(const unsigned long long*)&Et2_s[(tl + tt) * NU + k];
            c[tt][0] = fma2(a, lo.x, c[tt][0]);
            c[tt][1] = fma2(a, lo.y, c[tt][1]);
            c[tt][2] = fma2(a, hi.x, c[tt][2]);
            c[tt][3] = fma2(a, hi.y, c[tt][3]);
        }
    }

    #pragma unroll
    for (int tt = 0; tt < 4; tt++) {
        float* o = out + (size_t)(b * NT + t0 + tl + tt) * ND;
        ((ulonglong2*)o)[lane]      = make_ulonglong2(c[tt][0], c[tt][1]);
        ((ulonglong2*)o)[lane + 32] = make_ulonglong2(c[tt][2], c[tt][3]);
    }
}

// ---------------------------------------------------------------------------
// Launch
// ---------------------------------------------------------------------------
extern "C" void kernel_launch(void* const* d_in, const int* in_sizes, int n_in,
                              void* d_out, int out_size)
{
    const float* knw = (const float*)d_in[0];   // knowledge_onehot [16,128,256]
    const float* enc = (const float*)d_in[1];   // encoder_outputs  [16,256,256]
    const float* W1  = (const float*)d_in[2];
    const float* b1  = (const float*)d_in[3];
    const float* W2  = (const float*)d_in[4];
    const float* b2  = (const float*)d_in[5];
    const float* V   = (const float*)d_in[6];
    // d_in[7] = bV: cancels in softmax. Unused.

    if (n_in >= 2 && in_sizes[0] == NB * NT * ND && in_sizes[1] == NB * NK * ND) {
        const float* tmp = knw; knw = enc; enc = tmp;
    }

    // 32768 + 16384 + 8192 + 256 floats = 230400 bytes
    const int smem_bytes = (NK * ND + NU * NK + 32 * NU * 2 + NU * 2) * (int)sizeof(float);
    cudaFuncSetAttribute(fused_kernel, cudaFuncAttributeMaxDynamicSharedMemorySize,
                         smem_bytes);

    proj_kernel<<<384, 256>>>(enc, knw, W1, b1, W2, b2);

    dim3 grid(NT / 32, NB);
    fused_kernel<<<grid, 256, smem_bytes>>>(knw, V, (float*)d_out);

    (void)n_in; (void)out_size;
}